// round 14
// baseline (speedup 1.0000x reference)
#include <cuda_runtime.h>
#include <cuda_fp16.h>
#include <cstdint>

// ---------------------------------------------------------------------------
// Problem constants
// ---------------------------------------------------------------------------
#define B_ 4
#define T_ 160
#define U_ 80
#define DE 640
#define DTOT 1280
#define HH 640
#define VV 1024
#define TU (T_ * U_)          // 12800
#define MTOT (B_ * TU)        // 51200

// Joint GEMM tiling (warp-specialized)
#define BM 256
#define BN 128
#define BK 64
#define KITERS (HH / BK)      // 10
#define STAGES 3

// ---------------------------------------------------------------------------
// Device scratch
// ---------------------------------------------------------------------------
__device__ float g_pe[B_ * T_ * HH];
__device__ float g_pd[B_ * U_ * HH];
__device__ __align__(16) __half g_Ae[B_ * T_ * DE];       // fp16(enc)
__device__ __align__(16) __half g_Ad[B_ * U_ * DE];       // fp16(dec)
__device__ __align__(16) __half g_W1T[HH * DTOT];         // W1^T [h][d]
__device__ __align__(16) __half g_A[(size_t)MTOT * HH];   // fp16(tanh(...))
__device__ __align__(16) __half g_B[VV * HH];             // W2^T fp16 [n][k]

// ---------------------------------------------------------------------------
// Helpers
// ---------------------------------------------------------------------------
__device__ __forceinline__ uint32_t smem_u32(const void* p) {
    uint32_t a;
    asm("{ .reg .u64 t; cvta.to.shared.u64 t, %1; cvt.u32.u64 %0, t; }"
        : "=r"(a) : "l"(p));
    return a;
}

__device__ __forceinline__ float fast_tanh(float x) {
    float e;
    asm("ex2.approx.f32 %0, %1;" : "=f"(e) : "f"(x * 2.885390081777927f));
    float r;
    asm("rcp.approx.f32 %0, %1;" : "=f"(r) : "f"(e + 1.0f));
    return fmaf(-2.0f, r, 1.0f);
}

#define CP_ASYNC16(saddr, gptr) \
    asm volatile("cp.async.cg.shared.global [%0], [%1], 16;" \
                 :: "r"(saddr), "l"(gptr))
#define CP_COMMIT()  asm volatile("cp.async.commit_group;" ::: "memory")
#define CP_WAIT1()   asm volatile("cp.async.wait_group 1;" ::: "memory")
#define CP_WAIT0()   asm volatile("cp.async.wait_group 0;" ::: "memory")

#define LDSM4(r0, r1, r2, r3, a) \
    asm volatile("ldmatrix.sync.aligned.m8n8.x4.shared.b16 {%0,%1,%2,%3}, [%4];" \
                 : "=r"(r0), "=r"(r1), "=r"(r2), "=r"(r3) : "r"(a))

#define MMA16816(d, a, b0, b1) \
    asm volatile("mma.sync.aligned.m16n8k16.row.col.f32.f16.f16.f32 " \
                 "{%0,%1,%2,%3}, {%4,%5,%6,%7}, {%8,%9}, {%0,%1,%2,%3};" \
                 : "+f"((d)[0]), "+f"((d)[1]), "+f"((d)[2]), "+f"((d)[3]) \
                 : "r"((a)[0]), "r"((a)[1]), "r"((a)[2]), "r"((a)[3]), \
                   "r"(b0), "r"(b1))

// ---------------------------------------------------------------------------
// Stage 0: prep_static — W1 transpose + enc/dec fp16 conversion. 350 CTAs.
// ---------------------------------------------------------------------------
__global__ void __launch_bounds__(256)
prep_static(const float* __restrict__ enc,
            const float* __restrict__ dec,
            const float* __restrict__ W1,
            __half* __restrict__ Ae,
            __half* __restrict__ Ad,
            __half* __restrict__ W1T)
{
    const int tid = threadIdx.x;
    const int bx  = blockIdx.x;

    if (bx < 200) {                       // W1: [1280,640] -> g_W1T[h][d]
        __shared__ float tile[64][65];
        const int h0 = (bx % 10) * 64;
        const int d0 = (bx / 10) * 64;
        const int x  = tid & 63;
        const int yq = tid >> 6;
        #pragma unroll
        for (int j = 0; j < 16; j++) {
            int r = yq + j * 4;
            tile[r][x] = W1[(size_t)(d0 + r) * HH + h0 + x];
        }
        __syncthreads();
        #pragma unroll
        for (int j = 0; j < 16; j++) {
            int ny = yq + j * 4;
            W1T[(size_t)(h0 + ny) * DTOT + d0 + x] =
                __float2half_rn(tile[x][ny]);
        }
        return;
    }

    const int cb = bx - 200;
    const float* __restrict__ src;
    __half* __restrict__ dst;
    size_t off;
    if (cb < 100) { src = enc; dst = Ae; off = (size_t)cb * 4096; }
    else          { src = dec; dst = Ad; off = (size_t)(cb - 100) * 4096; }

    #pragma unroll
    for (int i = 0; i < 4; i++) {
        const size_t idx = off + (size_t)i * 1024 + tid * 4;
        float4 v = *(const float4*)&src[idx];
        __half h[4];
        h[0] = __float2half_rn(v.x);
        h[1] = __float2half_rn(v.y);
        h[2] = __float2half_rn(v.z);
        h[3] = __float2half_rn(v.w);
        *(uint2*)&dst[idx] = *(uint2*)h;
    }
}

// ---------------------------------------------------------------------------
// Stage 1: HMMA projection GEMM + W2 transpose (overlapped in one grid).
// ---------------------------------------------------------------------------
#define PSTG 24576u
#define PROJ_SMEM (3 * 24576)

__device__ __forceinline__ void proj_load(uint32_t sbuf,
                                          const __half* __restrict__ aB,
                                          const __half* __restrict__ bB,
                                          int k0)
{
    const int tid = threadIdx.x;
    #pragma unroll
    for (int i = 0; i < 4; i++) {
        int ci = tid + i * 128;
        int row = ci >> 3;
        int ck = ci & 7;
        uint32_t so = sbuf + row * 128 + ((ck ^ (row & 7)) << 4);
        CP_ASYNC16(so, aB + (size_t)row * DE + k0 + ck * 8);
    }
    #pragma unroll
    for (int i = 0; i < 8; i++) {
        int ci = tid + i * 128;
        int row = ci >> 3;
        int ck = ci & 7;
        uint32_t so = sbuf + 8192u + row * 128 + ((ck ^ (row & 7)) << 4);
        CP_ASYNC16(so, bB + (size_t)row * DTOT + k0 + ck * 8);
    }
}

__global__ void __launch_bounds__(128, 2)
proj_gemm(const __half* __restrict__ Ae,
          const __half* __restrict__ Ad,
          const __half* __restrict__ W1T,
          const float* __restrict__ b1,
          const float* __restrict__ W2,
          float* __restrict__ pe,
          float* __restrict__ pd,
          __half* __restrict__ Bt)
{
    extern __shared__ __align__(1024) char smem[];
    const int tid = threadIdx.x;

    if (blockIdx.y >= 15) {
        // ---- W2 transpose tile: Bt[n][k] = fp16(W2[k][n]), 64x64 ----
        float (*tile)[65] = reinterpret_cast<float(*)[65]>(smem);
        const int tt = (blockIdx.y - 15) * 5 + blockIdx.x;
        const int n0 = (tt & 15) * 64;
        const int k0 = (tt >> 4) * 64;
        const int x  = tid & 63;
        const int yq = tid >> 6;
        #pragma unroll
        for (int j = 0; j < 32; j++) {
            int r = yq + j * 2;
            tile[r][x] = W2[(size_t)(k0 + r) * VV + n0 + x];
        }
        __syncthreads();
        #pragma unroll
        for (int j = 0; j < 32; j++) {
            int ny = yq + j * 2;
            Bt[(size_t)(n0 + ny) * HH + k0 + x] = __float2half_rn(tile[x][ny]);
        }
        return;
    }

    const uint32_t sb = smem_u32(smem);
    const int lane = tid & 31;
    const int wn   = tid >> 5;
    const int n0   = blockIdx.x * 128;
    const bool is_dec = (blockIdx.y >= 10);
    const int m0   = (is_dec ? (blockIdx.y - 10) : blockIdx.y) * 64;
    const int dof  = is_dec ? DE : 0;

    const __half* __restrict__ aB = (is_dec ? Ad : Ae) + (size_t)m0 * DE;
    const __half* __restrict__ bB = W1T + (size_t)n0 * DTOT + dof;
    float* __restrict__ C         = is_dec ? pd : pe;

    const int lml = lane & 15;
    const int lmh = lane >> 4;

    float acc[4][4][4];
    #pragma unroll
    for (int a = 0; a < 4; a++)
        #pragma unroll
        for (int n = 0; n < 4; n++)
            #pragma unroll
            for (int i = 0; i < 4; i++) acc[a][n][i] = 0.0f;

    proj_load(sb,        aB, bB, 0);
    CP_COMMIT();
    proj_load(sb + PSTG, aB, bB, BK);
    CP_COMMIT();
    CP_WAIT1();
    __syncthreads();

    #pragma unroll
    for (int c = 0; c < 10; c++) {
        const uint32_t sbuf = sb + (uint32_t)(c % STAGES) * PSTG;

        if (c + 2 < 10) {
            proj_load(sb + (uint32_t)((c + 2) % STAGES) * PSTG,
                      aB, bB, (c + 2) * BK);
            CP_COMMIT();
        }

        #pragma unroll
        for (int ks = 0; ks < 4; ks++) {
            const int ck = 2 * ks + lmh;

            uint32_t af[4][4];
            #pragma unroll
            for (int a = 0; a < 4; a++) {
                uint32_t row = (uint32_t)(a * 16 + lml);
                LDSM4(af[a][0], af[a][1], af[a][2], af[a][3],
                      sbuf + row * 128 + (uint32_t)((ck ^ (row & 7)) << 4));
            }
            uint32_t bf[2][4];
            #pragma unroll
            for (int p = 0; p < 2; p++) {
                uint32_t row = (uint32_t)(wn * 32 + p * 16 + lml);
                LDSM4(bf[p][0], bf[p][1], bf[p][2], bf[p][3],
                      sbuf + 8192u + row * 128 +
                      (uint32_t)((ck ^ (row & 7)) << 4));
            }
            #pragma unroll
            for (int a = 0; a < 4; a++)
                #pragma unroll
                for (int n = 0; n < 4; n++) {
                    int p = n >> 1, s = n & 1;
                    MMA16816(acc[a][n], af[a], bf[p][s], bf[p][s + 2]);
                }
        }

        if (c + 2 < 10) CP_WAIT1();
        else            CP_WAIT0();
        __syncthreads();
    }

    #pragma unroll
    for (int n = 0; n < 4; n++) {
        const int col = n0 + wn * 32 + n * 8 + (lane & 3) * 2;
        float2 bb = make_float2(0.0f, 0.0f);
        if (is_dec) bb = *(const float2*)&b1[col];
        #pragma unroll
        for (int a = 0; a < 4; a++) {
            const int r0 = m0 + a * 16 + (lane >> 2);
            float2 o0 = { acc[a][n][0] + bb.x, acc[a][n][1] + bb.y };
            float2 o1 = { acc[a][n][2] + bb.x, acc[a][n][3] + bb.y };
            *(float2*)&C[(size_t)r0 * HH + col]       = o0;
            *(float2*)&C[(size_t)(r0 + 8) * HH + col] = o1;
        }
    }
}

// ---------------------------------------------------------------------------
// Stage 1.5: tiled A-prep. A = fp16(tanh(pe + pd)). grid (U/16, T/16, B*5).
// ---------------------------------------------------------------------------
__global__ void __launch_bounds__(256)
prep_a(__half* __restrict__ A)
{
    __shared__ float4 pe4[16][33];
    __shared__ float4 pd4[16][33];

    const int u0 = blockIdx.x * 16;
    const int t0 = blockIdx.y * 16;
    const int b  = blockIdx.z / 5;
    const int h0 = (blockIdx.z - b * 5) * 128;

    const int tid = threadIdx.x;

    {
        const int r  = tid >> 4;
        const int c4 = tid & 15;
        const float4* pe_g = (const float4*)&g_pe[(size_t)(b * T_ + t0 + r) * HH + h0];
        const float4* pd_g = (const float4*)&g_pd[(size_t)(b * U_ + u0 + r) * HH + h0];
        pe4[r][c4]      = pe_g[c4];
        pe4[r][c4 + 16] = pe_g[c4 + 16];
        pd4[r][c4]      = pd_g[c4];
        pd4[r][c4 + 16] = pd_g[c4 + 16];
    }
    __syncthreads();

    const int u_l = tid >> 4;
    const int seg = tid & 15;

    const float4 d0 = pd4[u_l][seg * 2];
    const float4 d1 = pd4[u_l][seg * 2 + 1];

    #pragma unroll
    for (int t_l = 0; t_l < 16; t_l++) {
        const float4 e0 = pe4[t_l][seg * 2];
        const float4 e1 = pe4[t_l][seg * 2 + 1];

        __half h[8];
        h[0] = __float2half_rn(fast_tanh(e0.x + d0.x));
        h[1] = __float2half_rn(fast_tanh(e0.y + d0.y));
        h[2] = __float2half_rn(fast_tanh(e0.z + d0.z));
        h[3] = __float2half_rn(fast_tanh(e0.w + d0.w));
        h[4] = __float2half_rn(fast_tanh(e1.x + d1.x));
        h[5] = __float2half_rn(fast_tanh(e1.y + d1.y));
        h[6] = __float2half_rn(fast_tanh(e1.z + d1.z));
        h[7] = __float2half_rn(fast_tanh(e1.w + d1.w));

        const size_t row = (size_t)b * TU + (t0 + t_l) * U_ + u0 + u_l;
        *(uint4*)&A[row * HH + h0 + seg * 8] = *(uint4*)h;
    }
}

// ---------------------------------------------------------------------------
// Stage 2: warp-specialized HMMA joint GEMM.
// BM=256, BN=128, BK=64; 288 threads = 8 consumer warps (4M x 2N, 64x64
// warp tiles; pure LDSM+MMA) + 1 producer warp (all cp.async).
// 3-stage pipeline (A 32KB + B 16KB per stage = 48KB; 144KB total, 1 CTA/SM).
// Consumers issue ZERO load/address instructions in the mainloop.
// ---------------------------------------------------------------------------
#define JSTG 49152u
#define JSMEM (STAGES * 49152)

__device__ __forceinline__ void prod_load(uint32_t sbuf,
                                          const __half* __restrict__ aB,
                                          const __half* __restrict__ bB,
                                          int k0, int lane)
{
    // A tile: 256 rows x 8 chunks = 2048, 64 per lane
    #pragma unroll
    for (int j = 0; j < 64; j++) {
        int ci = lane + j * 32;
        int row = ci >> 3;
        int ck = ci & 7;
        uint32_t so = sbuf + row * 128 + ((ck ^ (row & 7)) << 4);
        CP_ASYNC16(so, aB + (size_t)row * HH + k0 + ck * 8);
    }
    // B tile: 128 rows x 8 chunks = 1024, 32 per lane
    #pragma unroll
    for (int j = 0; j < 32; j++) {
        int ci = lane + j * 32;
        int row = ci >> 3;
        int ck = ci & 7;
        uint32_t so = sbuf + 32768u + row * 128 + ((ck ^ (row & 7)) << 4);
        CP_ASYNC16(so, bB + (size_t)row * HH + k0 + ck * 8);
    }
}

__global__ void __launch_bounds__(288, 1)
joint_gemm(const __half* __restrict__ A,
           const __half* __restrict__ B,
           const float* __restrict__ b2,
           float* __restrict__ out)
{
    extern __shared__ __align__(1024) char smem[];
    const uint32_t sb = smem_u32(smem);

    const int tid  = threadIdx.x;
    const int lane = tid & 31;
    const int wid  = tid >> 5;
    const int n0   = blockIdx.x * BN;
    const int m0   = blockIdx.y * BM;

    const __half* __restrict__ aB = A + (size_t)m0 * HH;
    const __half* __restrict__ bB = B + (size_t)n0 * HH;

    if (wid == 8) {
        // ---------------- producer warp ----------------
        prod_load(sb,        aB, bB, 0,  lane);
        CP_COMMIT();
        prod_load(sb + JSTG, aB, bB, BK, lane);
        CP_COMMIT();
        CP_WAIT1();                       // stage 0 complete
        __syncthreads();                  // publish stage 0

        #pragma unroll
        for (int c = 0; c < KITERS; c++) {
            if (c + 2 < KITERS) {
                prod_load(sb + (uint32_t)((c + 2) % STAGES) * JSTG,
                          aB, bB, (c + 2) * BK, lane);
                CP_COMMIT();
                CP_WAIT1();               // stage c+1 complete
            } else {
                CP_WAIT0();               // final stages complete
            }
            __syncthreads();              // publish stage c+1 / consume gate
        }
        return;
    }

    // ---------------- consumer warps ----------------
    const int wm = wid & 3;               // 0..3 -> 64-row stripes
    const int wn = wid >> 2;               // 0..1 -> 64-col stripes
    const int lml = lane & 15;
    const int lmh = lane >> 4;

    float acc[4][8][4];
    #pragma unroll
    for (int a = 0; a < 4; a++)
        #pragma unroll
        for (int n = 0; n < 8; n++)
            #pragma unroll
            for (int i = 0; i < 4; i++) acc[a][n][i] = 0.0f;

    __syncthreads();                      // stage 0 ready

    #pragma unroll
    for (int c = 0; c < KITERS; c++) {
        const uint32_t sbuf = sb + (uint32_t)(c % STAGES) * JSTG;

        #pragma unroll
        for (int ks = 0; ks < 4; ks++) {
            const int ck = 2 * ks + lmh;

            uint32_t af[4][4];
            #pragma unroll
            for (int a = 0; a < 4; a++) {
                uint32_t row = (uint32_t)(wm * 64 + a * 16 + lml);
                LDSM4(af[a][0], af[a][1], af[a][2], af[a][3],
                      sbuf + row * 128 + (uint32_t)((ck ^ (row & 7)) << 4));
            }
            uint32_t bf[4][4];
            #pragma unroll
            for (int p = 0; p < 4; p++) {
                uint32_t row = (uint32_t)(wn * 64 + p * 16 + lml);
                LDSM4(bf[p][0], bf[p][1], bf[p][2], bf[p][3],
                      sbuf + 32768u + row * 128 +
                      (uint32_t)((ck ^ (row & 7)) << 4));
            }
            #pragma unroll
            for (int a = 0; a < 4; a++)
                #pragma unroll
                for (int n = 0; n < 8; n++) {
                    int p = n >> 1, s = n & 1;
                    MMA16816(acc[a][n], af[a], bf[p][s], bf[p][s + 2]);
                }
        }

        __syncthreads();                  // done with stage c; next published
    }

    // epilogue: +b2, direct stores
    #pragma unroll
    for (int n = 0; n < 8; n++) {
        const int col = n0 + wn * 64 + n * 8 + (lane & 3) * 2;
        const float2 bb = *(const float2*)&b2[col];
        #pragma unroll
        for (int a = 0; a < 4; a++) {
            const size_t r0 = (size_t)m0 + wm * 64 + a * 16 + (lane >> 2);
            float2 o0 = { acc[a][n][0] + bb.x, acc[a][n][1] + bb.y };
            float2 o1 = { acc[a][n][2] + bb.x, acc[a][n][3] + bb.y };
            *(float2*)&out[r0 * VV + col]       = o0;
            *(float2*)&out[(r0 + 8) * VV + col] = o1;
        }
    }
}

// ---------------------------------------------------------------------------
// Launch: 4 kernels
// ---------------------------------------------------------------------------
extern "C" void kernel_launch(void* const* d_in, const int* in_sizes, int n_in,
                              void* d_out, int out_size)
{
    const float* enc = (const float*)d_in[0];
    const float* dec = (const float*)d_in[1];
    const float* W1  = (const float*)d_in[2];
    const float* b1  = (const float*)d_in[3];
    const float* W2  = (const float*)d_in[4];
    const float* b2  = (const float*)d_in[5];
    float* out = (float*)d_out;

    float *pe = nullptr, *pd = nullptr;
    __half *ga = nullptr, *gb = nullptr, *gae = nullptr, *gad = nullptr,
           *gw1t = nullptr;
    cudaGetSymbolAddress((void**)&pe,   g_pe);
    cudaGetSymbolAddress((void**)&pd,   g_pd);
    cudaGetSymbolAddress((void**)&ga,   g_A);
    cudaGetSymbolAddress((void**)&gb,   g_B);
    cudaGetSymbolAddress((void**)&gae,  g_Ae);
    cudaGetSymbolAddress((void**)&gad,  g_Ad);
    cudaGetSymbolAddress((void**)&gw1t, g_W1T);

    cudaFuncSetAttribute(joint_gemm,
                         cudaFuncAttributeMaxDynamicSharedMemorySize, JSMEM);
    cudaFuncSetAttribute(proj_gemm,
                         cudaFuncAttributeMaxDynamicSharedMemorySize, PROJ_SMEM);

    prep_static<<<350, 256>>>(enc, dec, W1, gae, gad, gw1t);
    proj_gemm<<<dim3(HH / 128, 47), 128, PROJ_SMEM>>>(gae, gad, gw1t, b1, W2,
                                                      pe, pd, gb);
    prep_a<<<dim3(U_ / 16, T_ / 16, B_ * 5), 256>>>(ga);
    joint_gemm<<<dim3(VV / BN, MTOT / BM), 288, JSMEM>>>(ga, gb, b2, out);
}

// round 15
// speedup vs baseline: 1.2951x; 1.2951x over previous
#include <cuda_runtime.h>
#include <cuda_fp16.h>
#include <cstdint>

// ---------------------------------------------------------------------------
// Problem constants
// ---------------------------------------------------------------------------
#define B_ 4
#define T_ 160
#define U_ 80
#define DE 640
#define DTOT 1280
#define HH 640
#define VV 1024
#define TU (T_ * U_)          // 12800
#define MTOT (B_ * TU)        // 51200

// Joint GEMM tiling
#define BM 128
#define BN 128
#define BK 64
#define KITERS (HH / BK)      // 10
#define STAGES 3

// ---------------------------------------------------------------------------
// Device scratch
// ---------------------------------------------------------------------------
__device__ float g_pe[B_ * T_ * HH];
__device__ float g_pd[B_ * U_ * HH];
__device__ __align__(16) __half g_Ae[B_ * T_ * DE];       // fp16(enc)
__device__ __align__(16) __half g_Ad[B_ * U_ * DE];       // fp16(dec)
__device__ __align__(16) __half g_W1T[HH * DTOT];         // W1^T [h][d]
__device__ __align__(16) __half g_A[(size_t)MTOT * HH];   // fp16(tanh(...))
__device__ __align__(16) __half g_B[VV * HH];             // W2^T fp16 [n][k]

// ---------------------------------------------------------------------------
// Helpers
// ---------------------------------------------------------------------------
__device__ __forceinline__ uint32_t smem_u32(const void* p) {
    uint32_t a;
    asm("{ .reg .u64 t; cvta.to.shared.u64 t, %1; cvt.u32.u64 %0, t; }"
        : "=r"(a) : "l"(p));
    return a;
}

__device__ __forceinline__ float fast_tanh(float x) {
    float e;
    asm("ex2.approx.f32 %0, %1;" : "=f"(e) : "f"(x * 2.885390081777927f));
    float r;
    asm("rcp.approx.f32 %0, %1;" : "=f"(r) : "f"(e + 1.0f));
    return fmaf(-2.0f, r, 1.0f);
}

#define CP_ASYNC16(saddr, gptr) \
    asm volatile("cp.async.cg.shared.global [%0], [%1], 16;" \
                 :: "r"(saddr), "l"(gptr))
#define CP_COMMIT()  asm volatile("cp.async.commit_group;" ::: "memory")
#define CP_WAIT1()   asm volatile("cp.async.wait_group 1;" ::: "memory")
#define CP_WAIT0()   asm volatile("cp.async.wait_group 0;" ::: "memory")

#define LDSM4(r0, r1, r2, r3, a) \
    asm volatile("ldmatrix.sync.aligned.m8n8.x4.shared.b16 {%0,%1,%2,%3}, [%4];" \
                 : "=r"(r0), "=r"(r1), "=r"(r2), "=r"(r3) : "r"(a))

#define MMA16816(d, a, b0, b1) \
    asm volatile("mma.sync.aligned.m16n8k16.row.col.f32.f16.f16.f32 " \
                 "{%0,%1,%2,%3}, {%4,%5,%6,%7}, {%8,%9}, {%0,%1,%2,%3};" \
                 : "+f"((d)[0]), "+f"((d)[1]), "+f"((d)[2]), "+f"((d)[3]) \
                 : "r"((a)[0]), "r"((a)[1]), "r"((a)[2]), "r"((a)[3]), \
                   "r"(b0), "r"(b1))

// ---------------------------------------------------------------------------
// Stage 0: prep_static — W1 transpose + enc/dec fp16 conversion. 350 CTAs.
// ---------------------------------------------------------------------------
__global__ void __launch_bounds__(256)
prep_static(const float* __restrict__ enc,
            const float* __restrict__ dec,
            const float* __restrict__ W1,
            __half* __restrict__ Ae,
            __half* __restrict__ Ad,
            __half* __restrict__ W1T)
{
    const int tid = threadIdx.x;
    const int bx  = blockIdx.x;

    if (bx < 200) {                       // W1: [1280,640] -> g_W1T[h][d]
        __shared__ float tile[64][65];
        const int h0 = (bx % 10) * 64;
        const int d0 = (bx / 10) * 64;
        const int x  = tid & 63;
        const int yq = tid >> 6;
        #pragma unroll
        for (int j = 0; j < 16; j++) {
            int r = yq + j * 4;
            tile[r][x] = W1[(size_t)(d0 + r) * HH + h0 + x];
        }
        __syncthreads();
        #pragma unroll
        for (int j = 0; j < 16; j++) {
            int ny = yq + j * 4;
            W1T[(size_t)(h0 + ny) * DTOT + d0 + x] =
                __float2half_rn(tile[x][ny]);
        }
        return;
    }

    const int cb = bx - 200;
    const float* __restrict__ src;
    __half* __restrict__ dst;
    size_t off;
    if (cb < 100) { src = enc; dst = Ae; off = (size_t)cb * 4096; }
    else          { src = dec; dst = Ad; off = (size_t)(cb - 100) * 4096; }

    #pragma unroll
    for (int i = 0; i < 4; i++) {
        const size_t idx = off + (size_t)i * 1024 + tid * 4;
        float4 v = *(const float4*)&src[idx];
        __half h[4];
        h[0] = __float2half_rn(v.x);
        h[1] = __float2half_rn(v.y);
        h[2] = __float2half_rn(v.z);
        h[3] = __float2half_rn(v.w);
        *(uint2*)&dst[idx] = *(uint2*)h;
    }
}

// ---------------------------------------------------------------------------
// Stage 1: HMMA projection GEMM + W2 transpose (overlapped in one grid).
// ---------------------------------------------------------------------------
#define PSTG 24576u
#define PROJ_SMEM (3 * 24576)

__device__ __forceinline__ void proj_load(uint32_t sbuf,
                                          const __half* __restrict__ aB,
                                          const __half* __restrict__ bB,
                                          int k0)
{
    const int tid = threadIdx.x;
    #pragma unroll
    for (int i = 0; i < 4; i++) {
        int ci = tid + i * 128;
        int row = ci >> 3;
        int ck = ci & 7;
        uint32_t so = sbuf + row * 128 + ((ck ^ (row & 7)) << 4);
        CP_ASYNC16(so, aB + (size_t)row * DE + k0 + ck * 8);
    }
    #pragma unroll
    for (int i = 0; i < 8; i++) {
        int ci = tid + i * 128;
        int row = ci >> 3;
        int ck = ci & 7;
        uint32_t so = sbuf + 8192u + row * 128 + ((ck ^ (row & 7)) << 4);
        CP_ASYNC16(so, bB + (size_t)row * DTOT + k0 + ck * 8);
    }
}

__global__ void __launch_bounds__(128, 2)
proj_gemm(const __half* __restrict__ Ae,
          const __half* __restrict__ Ad,
          const __half* __restrict__ W1T,
          const float* __restrict__ b1,
          const float* __restrict__ W2,
          float* __restrict__ pe,
          float* __restrict__ pd,
          __half* __restrict__ Bt)
{
    extern __shared__ __align__(1024) char smem[];
    const int tid = threadIdx.x;

    if (blockIdx.y >= 15) {
        // ---- W2 transpose tile: Bt[n][k] = fp16(W2[k][n]), 64x64 ----
        float (*tile)[65] = reinterpret_cast<float(*)[65]>(smem);
        const int tt = (blockIdx.y - 15) * 5 + blockIdx.x;
        const int n0 = (tt & 15) * 64;
        const int k0 = (tt >> 4) * 64;
        const int x  = tid & 63;
        const int yq = tid >> 6;
        #pragma unroll
        for (int j = 0; j < 32; j++) {
            int r = yq + j * 2;
            tile[r][x] = W2[(size_t)(k0 + r) * VV + n0 + x];
        }
        __syncthreads();
        #pragma unroll
        for (int j = 0; j < 32; j++) {
            int ny = yq + j * 2;
            Bt[(size_t)(n0 + ny) * HH + k0 + x] = __float2half_rn(tile[x][ny]);
        }
        return;
    }

    const uint32_t sb = smem_u32(smem);
    const int lane = tid & 31;
    const int wn   = tid >> 5;
    const int n0   = blockIdx.x * 128;
    const bool is_dec = (blockIdx.y >= 10);
    const int m0   = (is_dec ? (blockIdx.y - 10) : blockIdx.y) * 64;
    const int dof  = is_dec ? DE : 0;

    const __half* __restrict__ aB = (is_dec ? Ad : Ae) + (size_t)m0 * DE;
    const __half* __restrict__ bB = W1T + (size_t)n0 * DTOT + dof;
    float* __restrict__ C         = is_dec ? pd : pe;

    const int lml = lane & 15;
    const int lmh = lane >> 4;

    float acc[4][4][4];
    #pragma unroll
    for (int a = 0; a < 4; a++)
        #pragma unroll
        for (int n = 0; n < 4; n++)
            #pragma unroll
            for (int i = 0; i < 4; i++) acc[a][n][i] = 0.0f;

    proj_load(sb,        aB, bB, 0);
    CP_COMMIT();
    proj_load(sb + PSTG, aB, bB, BK);
    CP_COMMIT();
    CP_WAIT1();
    __syncthreads();

    #pragma unroll
    for (int c = 0; c < 10; c++) {
        const uint32_t sbuf = sb + (uint32_t)(c % STAGES) * PSTG;

        if (c + 2 < 10) {
            proj_load(sb + (uint32_t)((c + 2) % STAGES) * PSTG,
                      aB, bB, (c + 2) * BK);
            CP_COMMIT();
        }

        #pragma unroll
        for (int ks = 0; ks < 4; ks++) {
            const int ck = 2 * ks + lmh;

            uint32_t af[4][4];
            #pragma unroll
            for (int a = 0; a < 4; a++) {
                uint32_t row = (uint32_t)(a * 16 + lml);
                LDSM4(af[a][0], af[a][1], af[a][2], af[a][3],
                      sbuf + row * 128 + (uint32_t)((ck ^ (row & 7)) << 4));
            }
            uint32_t bf[2][4];
            #pragma unroll
            for (int p = 0; p < 2; p++) {
                uint32_t row = (uint32_t)(wn * 32 + p * 16 + lml);
                LDSM4(bf[p][0], bf[p][1], bf[p][2], bf[p][3],
                      sbuf + 8192u + row * 128 +
                      (uint32_t)((ck ^ (row & 7)) << 4));
            }
            #pragma unroll
            for (int a = 0; a < 4; a++)
                #pragma unroll
                for (int n = 0; n < 4; n++) {
                    int p = n >> 1, s = n & 1;
                    MMA16816(acc[a][n], af[a], bf[p][s], bf[p][s + 2]);
                }
        }

        if (c + 2 < 10) {
            CP_WAIT1();
            __syncthreads();
        } else if (c + 1 < 10) {
            CP_WAIT0();
            __syncthreads();
        }
        // last iter: no barrier — epilogue is register-only
    }

    #pragma unroll
    for (int n = 0; n < 4; n++) {
        const int col = n0 + wn * 32 + n * 8 + (lane & 3) * 2;
        float2 bb = make_float2(0.0f, 0.0f);
        if (is_dec) bb = *(const float2*)&b1[col];
        #pragma unroll
        for (int a = 0; a < 4; a++) {
            const int r0 = m0 + a * 16 + (lane >> 2);
            float2 o0 = { acc[a][n][0] + bb.x, acc[a][n][1] + bb.y };
            float2 o1 = { acc[a][n][2] + bb.x, acc[a][n][3] + bb.y };
            *(float2*)&C[(size_t)r0 * HH + col]       = o0;
            *(float2*)&C[(size_t)(r0 + 8) * HH + col] = o1;
        }
    }
}

// ---------------------------------------------------------------------------
// Stage 1.5: tiled A-prep. A = fp16(tanh(pe + pd)). grid (U/16, T/16, B*5).
// ---------------------------------------------------------------------------
__global__ void __launch_bounds__(256)
prep_a(__half* __restrict__ A)
{
    __shared__ float4 pe4[16][33];
    __shared__ float4 pd4[16][33];

    const int u0 = blockIdx.x * 16;
    const int t0 = blockIdx.y * 16;
    const int b  = blockIdx.z / 5;
    const int h0 = (blockIdx.z - b * 5) * 128;

    const int tid = threadIdx.x;

    {
        const int r  = tid >> 4;
        const int c4 = tid & 15;
        const float4* pe_g = (const float4*)&g_pe[(size_t)(b * T_ + t0 + r) * HH + h0];
        const float4* pd_g = (const float4*)&g_pd[(size_t)(b * U_ + u0 + r) * HH + h0];
        pe4[r][c4]      = pe_g[c4];
        pe4[r][c4 + 16] = pe_g[c4 + 16];
        pd4[r][c4]      = pd_g[c4];
        pd4[r][c4 + 16] = pd_g[c4 + 16];
    }
    __syncthreads();

    const int u_l = tid >> 4;
    const int seg = tid & 15;

    const float4 d0 = pd4[u_l][seg * 2];
    const float4 d1 = pd4[u_l][seg * 2 + 1];

    #pragma unroll
    for (int t_l = 0; t_l < 16; t_l++) {
        const float4 e0 = pe4[t_l][seg * 2];
        const float4 e1 = pe4[t_l][seg * 2 + 1];

        __half h[8];
        h[0] = __float2half_rn(fast_tanh(e0.x + d0.x));
        h[1] = __float2half_rn(fast_tanh(e0.y + d0.y));
        h[2] = __float2half_rn(fast_tanh(e0.z + d0.z));
        h[3] = __float2half_rn(fast_tanh(e0.w + d0.w));
        h[4] = __float2half_rn(fast_tanh(e1.x + d1.x));
        h[5] = __float2half_rn(fast_tanh(e1.y + d1.y));
        h[6] = __float2half_rn(fast_tanh(e1.z + d1.z));
        h[7] = __float2half_rn(fast_tanh(e1.w + d1.w));

        const size_t row = (size_t)b * TU + (t0 + t_l) * U_ + u0 + u_l;
        *(uint4*)&A[row * HH + h0 + seg * 8] = *(uint4*)h;
    }
}

// ---------------------------------------------------------------------------
// Stage 2: HMMA joint GEMM (R13 best config: fully unrolled, constant-folded
// addressing; BM=128, BN=128, BK=64; 128 thr = 4 warps, 64x64 warp tiles;
// 3-stage cp.async, 2 CTAs/SM). Micro-trims: b2 prefetched before mainloop,
// no barrier after final k-iter (epilogue is register-only).
// ---------------------------------------------------------------------------
#define STG_STRIDE 32768u
#define SMEM_TOTAL (STAGES * 32768)

__device__ __forceinline__ void load_buf(uint32_t sbuf,
                                         const __half* __restrict__ aB,
                                         const __half* __restrict__ bB,
                                         int k0)
{
    const int tid = threadIdx.x;
    #pragma unroll
    for (int i = 0; i < 8; i++) {
        int ci = tid + i * 128;
        int row = ci >> 3;
        int ck = ci & 7;
        uint32_t so = sbuf + row * 128 + ((ck ^ (row & 7)) << 4);
        CP_ASYNC16(so, aB + (size_t)row * HH + k0 + ck * 8);
    }
    #pragma unroll
    for (int i = 0; i < 8; i++) {
        int ci = tid + i * 128;
        int row = ci >> 3;
        int ck = ci & 7;
        uint32_t so = sbuf + 16384u + row * 128 + ((ck ^ (row & 7)) << 4);
        CP_ASYNC16(so, bB + (size_t)row * HH + k0 + ck * 8);
    }
}

__global__ void __launch_bounds__(128, 2)
joint_gemm(const __half* __restrict__ A,
           const __half* __restrict__ B,
           const float* __restrict__ b2,
           float* __restrict__ out)
{
    extern __shared__ __align__(1024) char smem[];
    const uint32_t sb = smem_u32(smem);

    const int tid  = threadIdx.x;
    const int lane = tid & 31;
    const int wid  = tid >> 5;
    const int wm   = wid & 1;
    const int wn   = wid >> 1;
    const int n0   = blockIdx.x * BN;
    const int m0   = blockIdx.y * BM;

    const __half* __restrict__ aB = A + (size_t)m0 * HH;
    const __half* __restrict__ bB = B + (size_t)n0 * HH;

    const int lml = lane & 15;
    const int lmh = lane >> 4;

    // prefetch epilogue bias (latency hidden under mainloop)
    float2 bb[8];
    #pragma unroll
    for (int n = 0; n < 8; n++)
        bb[n] = *(const float2*)&b2[n0 + wn * 64 + n * 8 + (lane & 3) * 2];

    float acc[4][8][4];
    #pragma unroll
    for (int a = 0; a < 4; a++)
        #pragma unroll
        for (int n = 0; n < 8; n++)
            #pragma unroll
            for (int i = 0; i < 4; i++) acc[a][n][i] = 0.0f;

    load_buf(sb,              aB, bB, 0);
    CP_COMMIT();
    load_buf(sb + STG_STRIDE, aB, bB, BK);
    CP_COMMIT();
    CP_WAIT1();
    __syncthreads();

    #pragma unroll
    for (int c = 0; c < KITERS; c++) {
        const uint32_t sbuf = sb + (uint32_t)(c % STAGES) * STG_STRIDE;

        if (c + 2 < KITERS) {
            load_buf(sb + (uint32_t)((c + 2) % STAGES) * STG_STRIDE,
                     aB, bB, (c + 2) * BK);
            CP_COMMIT();
        }

        #pragma unroll
        for (int ks = 0; ks < 4; ks++) {
            const int ck = 2 * ks + lmh;

            uint32_t af[4][4];
            #pragma unroll
            for (int a = 0; a < 4; a++) {
                uint32_t row = (uint32_t)(wm * 64 + a * 16 + lml);
                LDSM4(af[a][0], af[a][1], af[a][2], af[a][3],
                      sbuf + row * 128 + (uint32_t)((ck ^ (row & 7)) << 4));
            }
            uint32_t bf[4][4];
            #pragma unroll
            for (int p = 0; p < 4; p++) {
                uint32_t row = (uint32_t)(wn * 64 + p * 16 + lml);
                LDSM4(bf[p][0], bf[p][1], bf[p][2], bf[p][3],
                      sbuf + 16384u + row * 128 +
                      (uint32_t)((ck ^ (row & 7)) << 4));
            }
            #pragma unroll
            for (int a = 0; a < 4; a++)
                #pragma unroll
                for (int n = 0; n < 8; n++) {
                    int p = n >> 1, s = n & 1;
                    MMA16816(acc[a][n], af[a], bf[p][s], bf[p][s + 2]);
                }
        }

        if (c + 2 < KITERS) {
            CP_WAIT1();
            __syncthreads();
        } else if (c + 1 < KITERS) {
            CP_WAIT0();
            __syncthreads();
        }
        // last iter: no barrier — epilogue reads only registers
    }

    #pragma unroll
    for (int n = 0; n < 8; n++) {
        const int col = n0 + wn * 64 + n * 8 + (lane & 3) * 2;
        #pragma unroll
        for (int a = 0; a < 4; a++) {
            const size_t r0 = (size_t)m0 + wm * 64 + a * 16 + (lane >> 2);
            float2 o0 = { acc[a][n][0] + bb[n].x, acc[a][n][1] + bb[n].y };
            float2 o1 = { acc[a][n][2] + bb[n].x, acc[a][n][3] + bb[n].y };
            *(float2*)&out[r0 * VV + col]       = o0;
            *(float2*)&out[(r0 + 8) * VV + col] = o1;
        }
    }
}

// ---------------------------------------------------------------------------
// Launch: 4 kernels
// ---------------------------------------------------------------------------
extern "C" void kernel_launch(void* const* d_in, const int* in_sizes, int n_in,
                              void* d_out, int out_size)
{
    const float* enc = (const float*)d_in[0];
    const float* dec = (const float*)d_in[1];
    const float* W1  = (const float*)d_in[2];
    const float* b1  = (const float*)d_in[3];
    const float* W2  = (const float*)d_in[4];
    const float* b2  = (const float*)d_in[5];
    float* out = (float*)d_out;

    float *pe = nullptr, *pd = nullptr;
    __half *ga = nullptr, *gb = nullptr, *gae = nullptr, *gad = nullptr,
           *gw1t = nullptr;
    cudaGetSymbolAddress((void**)&pe,   g_pe);
    cudaGetSymbolAddress((void**)&pd,   g_pd);
    cudaGetSymbolAddress((void**)&ga,   g_A);
    cudaGetSymbolAddress((void**)&gb,   g_B);
    cudaGetSymbolAddress((void**)&gae,  g_Ae);
    cudaGetSymbolAddress((void**)&gad,  g_Ad);
    cudaGetSymbolAddress((void**)&gw1t, g_W1T);

    cudaFuncSetAttribute(joint_gemm,
                         cudaFuncAttributeMaxDynamicSharedMemorySize, SMEM_TOTAL);
    cudaFuncSetAttribute(proj_gemm,
                         cudaFuncAttributeMaxDynamicSharedMemorySize, PROJ_SMEM);

    prep_static<<<350, 256>>>(enc, dec, W1, gae, gad, gw1t);
    proj_gemm<<<dim3(HH / 128, 47), 128, PROJ_SMEM>>>(gae, gad, gw1t, b1, W2,
                                                      pe, pd, gb);
    prep_a<<<dim3(U_ / 16, T_ / 16, B_ * 5), 256>>>(ga);
    joint_gemm<<<dim3(VV / BN, MTOT / BM), 128, SMEM_TOTAL>>>(ga, gb, b2, out);
}

// round 16
// speedup vs baseline: 1.3350x; 1.0308x over previous
#include <cuda_runtime.h>
#include <cuda_fp16.h>
#include <cstdint>

// ---------------------------------------------------------------------------
// Problem constants
// ---------------------------------------------------------------------------
#define B_ 4
#define T_ 160
#define U_ 80
#define DE 640
#define DTOT 1280
#define HH 640
#define VV 1024
#define TU (T_ * U_)          // 12800
#define MTOT (B_ * TU)        // 51200

// Joint GEMM tiling
#define BM 128
#define BN 128
#define BK 64
#define KITERS (HH / BK)      // 10
#define STAGES 3

// ---------------------------------------------------------------------------
// Device scratch
// ---------------------------------------------------------------------------
__device__ float g_pe[B_ * T_ * HH];
__device__ float g_pd[B_ * U_ * HH];
__device__ __align__(16) __half g_Ae[B_ * T_ * DE];       // fp16(enc)
__device__ __align__(16) __half g_Ad[B_ * U_ * DE];       // fp16(dec)
__device__ __align__(16) __half g_W1T[HH * DTOT];         // W1^T [h][d]
__device__ __align__(16) __half g_A[(size_t)MTOT * HH];   // fp16(tanh(...))
__device__ __align__(16) __half g_B[VV * HH];             // W2^T fp16 [n][k]

// ---------------------------------------------------------------------------
// Helpers
// ---------------------------------------------------------------------------
__device__ __forceinline__ uint32_t smem_u32(const void* p) {
    uint32_t a;
    asm("{ .reg .u64 t; cvta.to.shared.u64 t, %1; cvt.u32.u64 %0, t; }"
        : "=r"(a) : "l"(p));
    return a;
}

__device__ __forceinline__ float fast_tanh(float x) {
    float e;
    asm("ex2.approx.f32 %0, %1;" : "=f"(e) : "f"(x * 2.885390081777927f));
    float r;
    asm("rcp.approx.f32 %0, %1;" : "=f"(r) : "f"(e + 1.0f));
    return fmaf(-2.0f, r, 1.0f);
}

#define CP_ASYNC16(saddr, gptr) \
    asm volatile("cp.async.cg.shared.global [%0], [%1], 16;" \
                 :: "r"(saddr), "l"(gptr))
#define CP_COMMIT()  asm volatile("cp.async.commit_group;" ::: "memory")
#define CP_WAIT1()   asm volatile("cp.async.wait_group 1;" ::: "memory")
#define CP_WAIT0()   asm volatile("cp.async.wait_group 0;" ::: "memory")

#define LDSM4(r0, r1, r2, r3, a) \
    asm volatile("ldmatrix.sync.aligned.m8n8.x4.shared.b16 {%0,%1,%2,%3}, [%4];" \
                 : "=r"(r0), "=r"(r1), "=r"(r2), "=r"(r3) : "r"(a))

#define MMA16816(d, a, b0, b1) \
    asm volatile("mma.sync.aligned.m16n8k16.row.col.f32.f16.f16.f32 " \
                 "{%0,%1,%2,%3}, {%4,%5,%6,%7}, {%8,%9}, {%0,%1,%2,%3};" \
                 : "+f"((d)[0]), "+f"((d)[1]), "+f"((d)[2]), "+f"((d)[3]) \
                 : "r"((a)[0]), "r"((a)[1]), "r"((a)[2]), "r"((a)[3]), \
                   "r"(b0), "r"(b1))

// ---------------------------------------------------------------------------
// Stage 0: prep_static — W1 transpose + enc/dec fp16 conversion. 350 CTAs.
// ---------------------------------------------------------------------------
__global__ void __launch_bounds__(256)
prep_static(const float* __restrict__ enc,
            const float* __restrict__ dec,
            const float* __restrict__ W1,
            __half* __restrict__ Ae,
            __half* __restrict__ Ad,
            __half* __restrict__ W1T)
{
    const int tid = threadIdx.x;
    const int bx  = blockIdx.x;

    if (bx < 200) {                       // W1: [1280,640] -> g_W1T[h][d]
        __shared__ float tile[64][65];
        const int h0 = (bx % 10) * 64;
        const int d0 = (bx / 10) * 64;
        const int x  = tid & 63;
        const int yq = tid >> 6;
        #pragma unroll
        for (int j = 0; j < 16; j++) {
            int r = yq + j * 4;
            tile[r][x] = W1[(size_t)(d0 + r) * HH + h0 + x];
        }
        __syncthreads();
        #pragma unroll
        for (int j = 0; j < 16; j++) {
            int ny = yq + j * 4;
            W1T[(size_t)(h0 + ny) * DTOT + d0 + x] =
                __float2half_rn(tile[x][ny]);
        }
        return;
    }

    const int cb = bx - 200;
    const float* __restrict__ src;
    __half* __restrict__ dst;
    size_t off;
    if (cb < 100) { src = enc; dst = Ae; off = (size_t)cb * 4096; }
    else          { src = dec; dst = Ad; off = (size_t)(cb - 100) * 4096; }

    #pragma unroll
    for (int i = 0; i < 4; i++) {
        const size_t idx = off + (size_t)i * 1024 + tid * 4;
        float4 v = *(const float4*)&src[idx];
        __half h[4];
        h[0] = __float2half_rn(v.x);
        h[1] = __float2half_rn(v.y);
        h[2] = __float2half_rn(v.z);
        h[3] = __float2half_rn(v.w);
        *(uint2*)&dst[idx] = *(uint2*)h;
    }
}

// ---------------------------------------------------------------------------
// Stage 1: HMMA projection GEMM + W2 transpose (overlapped in one grid).
// ---------------------------------------------------------------------------
#define PSTG 24576u
#define PROJ_SMEM (3 * 24576)

__device__ __forceinline__ void proj_load(uint32_t sbuf,
                                          const __half* __restrict__ aB,
                                          const __half* __restrict__ bB,
                                          int k0)
{
    const int tid = threadIdx.x;
    #pragma unroll
    for (int i = 0; i < 4; i++) {
        int ci = tid + i * 128;
        int row = ci >> 3;
        int ck = ci & 7;
        uint32_t so = sbuf + row * 128 + ((ck ^ (row & 7)) << 4);
        CP_ASYNC16(so, aB + (size_t)row * DE + k0 + ck * 8);
    }
    #pragma unroll
    for (int i = 0; i < 8; i++) {
        int ci = tid + i * 128;
        int row = ci >> 3;
        int ck = ci & 7;
        uint32_t so = sbuf + 8192u + row * 128 + ((ck ^ (row & 7)) << 4);
        CP_ASYNC16(so, bB + (size_t)row * DTOT + k0 + ck * 8);
    }
}

__global__ void __launch_bounds__(128, 2)
proj_gemm(const __half* __restrict__ Ae,
          const __half* __restrict__ Ad,
          const __half* __restrict__ W1T,
          const float* __restrict__ b1,
          const float* __restrict__ W2,
          float* __restrict__ pe,
          float* __restrict__ pd,
          __half* __restrict__ Bt)
{
    extern __shared__ __align__(1024) char smem[];
    const int tid = threadIdx.x;

    if (blockIdx.y >= 15) {
        // ---- W2 transpose tile: Bt[n][k] = fp16(W2[k][n]), 64x64 ----
        float (*tile)[65] = reinterpret_cast<float(*)[65]>(smem);
        const int tt = (blockIdx.y - 15) * 5 + blockIdx.x;
        const int n0 = (tt & 15) * 64;
        const int k0 = (tt >> 4) * 64;
        const int x  = tid & 63;
        const int yq = tid >> 6;
        #pragma unroll
        for (int j = 0; j < 32; j++) {
            int r = yq + j * 2;
            tile[r][x] = W2[(size_t)(k0 + r) * VV + n0 + x];
        }
        __syncthreads();
        #pragma unroll
        for (int j = 0; j < 32; j++) {
            int ny = yq + j * 2;
            Bt[(size_t)(n0 + ny) * HH + k0 + x] = __float2half_rn(tile[x][ny]);
        }
        return;
    }

    const uint32_t sb = smem_u32(smem);
    const int lane = tid & 31;
    const int wn   = tid >> 5;
    const int n0   = blockIdx.x * 128;
    const bool is_dec = (blockIdx.y >= 10);
    const int m0   = (is_dec ? (blockIdx.y - 10) : blockIdx.y) * 64;
    const int dof  = is_dec ? DE : 0;

    const __half* __restrict__ aB = (is_dec ? Ad : Ae) + (size_t)m0 * DE;
    const __half* __restrict__ bB = W1T + (size_t)n0 * DTOT + dof;
    float* __restrict__ C         = is_dec ? pd : pe;

    const int lml = lane & 15;
    const int lmh = lane >> 4;

    float acc[4][4][4];
    #pragma unroll
    for (int a = 0; a < 4; a++)
        #pragma unroll
        for (int n = 0; n < 4; n++)
            #pragma unroll
            for (int i = 0; i < 4; i++) acc[a][n][i] = 0.0f;

    proj_load(sb,        aB, bB, 0);
    CP_COMMIT();
    proj_load(sb + PSTG, aB, bB, BK);
    CP_COMMIT();
    CP_WAIT1();
    __syncthreads();

    #pragma unroll
    for (int c = 0; c < 10; c++) {
        const uint32_t sbuf = sb + (uint32_t)(c % STAGES) * PSTG;

        if (c + 2 < 10) {
            proj_load(sb + (uint32_t)((c + 2) % STAGES) * PSTG,
                      aB, bB, (c + 2) * BK);
            CP_COMMIT();
        }

        #pragma unroll
        for (int ks = 0; ks < 4; ks++) {
            const int ck = 2 * ks + lmh;

            uint32_t af[4][4];
            #pragma unroll
            for (int a = 0; a < 4; a++) {
                uint32_t row = (uint32_t)(a * 16 + lml);
                LDSM4(af[a][0], af[a][1], af[a][2], af[a][3],
                      sbuf + row * 128 + (uint32_t)((ck ^ (row & 7)) << 4));
            }
            uint32_t bf[2][4];
            #pragma unroll
            for (int p = 0; p < 2; p++) {
                uint32_t row = (uint32_t)(wn * 32 + p * 16 + lml);
                LDSM4(bf[p][0], bf[p][1], bf[p][2], bf[p][3],
                      sbuf + 8192u + row * 128 +
                      (uint32_t)((ck ^ (row & 7)) << 4));
            }
            #pragma unroll
            for (int a = 0; a < 4; a++)
                #pragma unroll
                for (int n = 0; n < 4; n++) {
                    int p = n >> 1, s = n & 1;
                    MMA16816(acc[a][n], af[a], bf[p][s], bf[p][s + 2]);
                }
        }

        if (c + 2 < 10) {
            CP_WAIT1();
            __syncthreads();
        } else if (c + 1 < 10) {
            CP_WAIT0();
            __syncthreads();
        }
    }

    #pragma unroll
    for (int n = 0; n < 4; n++) {
        const int col = n0 + wn * 32 + n * 8 + (lane & 3) * 2;
        float2 bb = make_float2(0.0f, 0.0f);
        if (is_dec) bb = *(const float2*)&b1[col];
        #pragma unroll
        for (int a = 0; a < 4; a++) {
            const int r0 = m0 + a * 16 + (lane >> 2);
            float2 o0 = { acc[a][n][0] + bb.x, acc[a][n][1] + bb.y };
            float2 o1 = { acc[a][n][2] + bb.x, acc[a][n][3] + bb.y };
            *(float2*)&C[(size_t)r0 * HH + col]       = o0;
            *(float2*)&C[(size_t)(r0 + 8) * HH + col] = o1;
        }
    }
}

// ---------------------------------------------------------------------------
// Stage 1.5: tiled A-prep. A = fp16(tanh(pe + pd)). grid (U/16, T/16, B*5).
// ---------------------------------------------------------------------------
__global__ void __launch_bounds__(256)
prep_a(__half* __restrict__ A)
{
    __shared__ float4 pe4[16][33];
    __shared__ float4 pd4[16][33];

    const int u0 = blockIdx.x * 16;
    const int t0 = blockIdx.y * 16;
    const int b  = blockIdx.z / 5;
    const int h0 = (blockIdx.z - b * 5) * 128;

    const int tid = threadIdx.x;

    {
        const int r  = tid >> 4;
        const int c4 = tid & 15;
        const float4* pe_g = (const float4*)&g_pe[(size_t)(b * T_ + t0 + r) * HH + h0];
        const float4* pd_g = (const float4*)&g_pd[(size_t)(b * U_ + u0 + r) * HH + h0];
        pe4[r][c4]      = pe_g[c4];
        pe4[r][c4 + 16] = pe_g[c4 + 16];
        pd4[r][c4]      = pd_g[c4];
        pd4[r][c4 + 16] = pd_g[c4 + 16];
    }
    __syncthreads();

    const int u_l = tid >> 4;
    const int seg = tid & 15;

    const float4 d0 = pd4[u_l][seg * 2];
    const float4 d1 = pd4[u_l][seg * 2 + 1];

    #pragma unroll
    for (int t_l = 0; t_l < 16; t_l++) {
        const float4 e0 = pe4[t_l][seg * 2];
        const float4 e1 = pe4[t_l][seg * 2 + 1];

        __half h[8];
        h[0] = __float2half_rn(fast_tanh(e0.x + d0.x));
        h[1] = __float2half_rn(fast_tanh(e0.y + d0.y));
        h[2] = __float2half_rn(fast_tanh(e0.z + d0.z));
        h[3] = __float2half_rn(fast_tanh(e0.w + d0.w));
        h[4] = __float2half_rn(fast_tanh(e1.x + d1.x));
        h[5] = __float2half_rn(fast_tanh(e1.y + d1.y));
        h[6] = __float2half_rn(fast_tanh(e1.z + d1.z));
        h[7] = __float2half_rn(fast_tanh(e1.w + d1.w));

        const size_t row = (size_t)b * TU + (t0 + t_l) * U_ + u0 + u_l;
        *(uint4*)&A[row * HH + h0 + seg * 8] = *(uint4*)h;
    }
}

// ---------------------------------------------------------------------------
// Stage 2: HMMA joint GEMM (R13/R15 config) with SPLIT prefetch issue:
// A-half after ks=0, B-half after ks=1 — spreads LDGSTS issue across the
// compute instead of a 16-deep front burst competing with the first LDSMs.
// ---------------------------------------------------------------------------
#define STG_STRIDE 32768u
#define SMEM_TOTAL (STAGES * 32768)

__device__ __forceinline__ void load_A_half(uint32_t sbuf,
                                            const __half* __restrict__ aB,
                                            int k0)
{
    const int tid = threadIdx.x;
    #pragma unroll
    for (int i = 0; i < 8; i++) {
        int ci = tid + i * 128;
        int row = ci >> 3;
        int ck = ci & 7;
        uint32_t so = sbuf + row * 128 + ((ck ^ (row & 7)) << 4);
        CP_ASYNC16(so, aB + (size_t)row * HH + k0 + ck * 8);
    }
}

__device__ __forceinline__ void load_B_half(uint32_t sbuf,
                                            const __half* __restrict__ bB,
                                            int k0)
{
    const int tid = threadIdx.x;
    #pragma unroll
    for (int i = 0; i < 8; i++) {
        int ci = tid + i * 128;
        int row = ci >> 3;
        int ck = ci & 7;
        uint32_t so = sbuf + 16384u + row * 128 + ((ck ^ (row & 7)) << 4);
        CP_ASYNC16(so, bB + (size_t)row * HH + k0 + ck * 8);
    }
}

__global__ void __launch_bounds__(128, 2)
joint_gemm(const __half* __restrict__ A,
           const __half* __restrict__ B,
           const float* __restrict__ b2,
           float* __restrict__ out)
{
    extern __shared__ __align__(1024) char smem[];
    const uint32_t sb = smem_u32(smem);

    const int tid  = threadIdx.x;
    const int lane = tid & 31;
    const int wid  = tid >> 5;
    const int wm   = wid & 1;
    const int wn   = wid >> 1;
    const int n0   = blockIdx.x * BN;
    const int m0   = blockIdx.y * BM;

    const __half* __restrict__ aB = A + (size_t)m0 * HH;
    const __half* __restrict__ bB = B + (size_t)n0 * HH;

    const int lml = lane & 15;
    const int lmh = lane >> 4;

    // prefetch epilogue bias (latency hidden under mainloop)
    float2 bb[8];
    #pragma unroll
    for (int n = 0; n < 8; n++)
        bb[n] = *(const float2*)&b2[n0 + wn * 64 + n * 8 + (lane & 3) * 2];

    float acc[4][8][4];
    #pragma unroll
    for (int a = 0; a < 4; a++)
        #pragma unroll
        for (int n = 0; n < 8; n++)
            #pragma unroll
            for (int i = 0; i < 4; i++) acc[a][n][i] = 0.0f;

    load_A_half(sb, aB, 0);
    load_B_half(sb, bB, 0);
    CP_COMMIT();
    load_A_half(sb + STG_STRIDE, aB, BK);
    load_B_half(sb + STG_STRIDE, bB, BK);
    CP_COMMIT();
    CP_WAIT1();
    __syncthreads();

    #pragma unroll
    for (int c = 0; c < KITERS; c++) {
        const uint32_t sbuf = sb + (uint32_t)(c % STAGES) * STG_STRIDE;
        const uint32_t pbuf = sb + (uint32_t)((c + 2) % STAGES) * STG_STRIDE;
        const bool do_pf = (c + 2 < KITERS);

        #pragma unroll
        for (int ks = 0; ks < 4; ks++) {
            const int ck = 2 * ks + lmh;

            uint32_t af[4][4];
            #pragma unroll
            for (int a = 0; a < 4; a++) {
                uint32_t row = (uint32_t)(wm * 64 + a * 16 + lml);
                LDSM4(af[a][0], af[a][1], af[a][2], af[a][3],
                      sbuf + row * 128 + (uint32_t)((ck ^ (row & 7)) << 4));
            }
            uint32_t bf[4][4];
            #pragma unroll
            for (int p = 0; p < 4; p++) {
                uint32_t row = (uint32_t)(wn * 64 + p * 16 + lml);
                LDSM4(bf[p][0], bf[p][1], bf[p][2], bf[p][3],
                      sbuf + 16384u + row * 128 +
                      (uint32_t)((ck ^ (row & 7)) << 4));
            }
            #pragma unroll
            for (int a = 0; a < 4; a++)
                #pragma unroll
                for (int n = 0; n < 8; n++) {
                    int p = n >> 1, s = n & 1;
                    MMA16816(acc[a][n], af[a], bf[p][s], bf[p][s + 2]);
                }

            // spread next-stage prefetch across the iteration
            if (do_pf && ks == 0) load_A_half(pbuf, aB, (c + 2) * BK);
            if (do_pf && ks == 1) {
                load_B_half(pbuf, bB, (c + 2) * BK);
                CP_COMMIT();
            }
        }

        if (c + 2 < KITERS) {
            CP_WAIT1();
            __syncthreads();
        } else if (c + 1 < KITERS) {
            CP_WAIT0();
            __syncthreads();
        }
        // last iter: no barrier — epilogue reads only registers
    }

    #pragma unroll
    for (int n = 0; n < 8; n++) {
        const int col = n0 + wn * 64 + n * 8 + (lane & 3) * 2;
        #pragma unroll
        for (int a = 0; a < 4; a++) {
            const size_t r0 = (size_t)m0 + wm * 64 + a * 16 + (lane >> 2);
            float2 o0 = { acc[a][n][0] + bb[n].x, acc[a][n][1] + bb[n].y };
            float2 o1 = { acc[a][n][2] + bb[n].x, acc[a][n][3] + bb[n].y };
            *(float2*)&out[r0 * VV + col]       = o0;
            *(float2*)&out[(r0 + 8) * VV + col] = o1;
        }
    }
}

// ---------------------------------------------------------------------------
// Launch: 4 kernels
// ---------------------------------------------------------------------------
extern "C" void kernel_launch(void* const* d_in, const int* in_sizes, int n_in,
                              void* d_out, int out_size)
{
    const float* enc = (const float*)d_in[0];
    const float* dec = (const float*)d_in[1];
    const float* W1  = (const float*)d_in[2];
    const float* b1  = (const float*)d_in[3];
    const float* W2  = (const float*)d_in[4];
    const float* b2  = (const float*)d_in[5];
    float* out = (float*)d_out;

    float *pe = nullptr, *pd = nullptr;
    __half *ga = nullptr, *gb = nullptr, *gae = nullptr, *gad = nullptr,
           *gw1t = nullptr;
    cudaGetSymbolAddress((void**)&pe,   g_pe);
    cudaGetSymbolAddress((void**)&pd,   g_pd);
    cudaGetSymbolAddress((void**)&ga,   g_A);
    cudaGetSymbolAddress((void**)&gb,   g_B);
    cudaGetSymbolAddress((void**)&gae,  g_Ae);
    cudaGetSymbolAddress((void**)&gad,  g_Ad);
    cudaGetSymbolAddress((void**)&gw1t, g_W1T);

    cudaFuncSetAttribute(joint_gemm,
                         cudaFuncAttributeMaxDynamicSharedMemorySize, SMEM_TOTAL);
    cudaFuncSetAttribute(proj_gemm,
                         cudaFuncAttributeMaxDynamicSharedMemorySize, PROJ_SMEM);

    prep_static<<<350, 256>>>(enc, dec, W1, gae, gad, gw1t);
    proj_gemm<<<dim3(HH / 128, 47), 128, PROJ_SMEM>>>(gae, gad, gw1t, b1, W2,
                                                      pe, pd, gb);
    prep_a<<<dim3(U_ / 16, T_ / 16, B_ * 5), 256>>>(ga);
    joint_gemm<<<dim3(VV / BN, MTOT / BM), 128, SMEM_TOTAL>>>(ga, gb, b2, out);
}

// round 17
// speedup vs baseline: 1.3492x; 1.0106x over previous
#include <cuda_runtime.h>
#include <cuda_fp16.h>
#include <cstdint>

// ---------------------------------------------------------------------------
// Problem constants
// ---------------------------------------------------------------------------
#define B_ 4
#define T_ 160
#define U_ 80
#define DE 640
#define DTOT 1280
#define HH 640
#define VV 1024
#define TU (T_ * U_)          // 12800
#define MTOT (B_ * TU)        // 51200

// Joint GEMM tiling
#define BM 128
#define BN 128
#define BK 64
#define KITERS (HH / BK)      // 10
#define STAGES 3

// ---------------------------------------------------------------------------
// Device scratch
// ---------------------------------------------------------------------------
__device__ float g_pe[B_ * T_ * HH];
__device__ float g_pd[B_ * U_ * HH];
__device__ __align__(16) __half g_Ae[B_ * T_ * DE];       // fp16(enc)
__device__ __align__(16) __half g_Ad[B_ * U_ * DE];       // fp16(dec)
__device__ __align__(16) __half g_W1T[HH * DTOT];         // W1^T [h][d]
__device__ __align__(16) __half g_A[(size_t)MTOT * HH];   // fp16(tanh(...))
__device__ __align__(16) __half g_B[VV * HH];             // W2^T fp16 [n][k]

// ---------------------------------------------------------------------------
// Helpers
// ---------------------------------------------------------------------------
__device__ __forceinline__ uint32_t smem_u32(const void* p) {
    uint32_t a;
    asm("{ .reg .u64 t; cvta.to.shared.u64 t, %1; cvt.u32.u64 %0, t; }"
        : "=r"(a) : "l"(p));
    return a;
}

__device__ __forceinline__ float fast_tanh(float x) {
    float e;
    asm("ex2.approx.f32 %0, %1;" : "=f"(e) : "f"(x * 2.885390081777927f));
    float r;
    asm("rcp.approx.f32 %0, %1;" : "=f"(r) : "f"(e + 1.0f));
    return fmaf(-2.0f, r, 1.0f);
}

#define CP_ASYNC16(saddr, gptr) \
    asm volatile("cp.async.cg.shared.global [%0], [%1], 16;" \
                 :: "r"(saddr), "l"(gptr))
#define CP_COMMIT()  asm volatile("cp.async.commit_group;" ::: "memory")
#define CP_WAIT1()   asm volatile("cp.async.wait_group 1;" ::: "memory")
#define CP_WAIT0()   asm volatile("cp.async.wait_group 0;" ::: "memory")

#define LDSM4(r0, r1, r2, r3, a) \
    asm volatile("ldmatrix.sync.aligned.m8n8.x4.shared.b16 {%0,%1,%2,%3}, [%4];" \
                 : "=r"(r0), "=r"(r1), "=r"(r2), "=r"(r3) : "r"(a))

#define MMA16816(d, a, b0, b1) \
    asm volatile("mma.sync.aligned.m16n8k16.row.col.f32.f16.f16.f32 " \
                 "{%0,%1,%2,%3}, {%4,%5,%6,%7}, {%8,%9}, {%0,%1,%2,%3};" \
                 : "+f"((d)[0]), "+f"((d)[1]), "+f"((d)[2]), "+f"((d)[3]) \
                 : "r"((a)[0]), "r"((a)[1]), "r"((a)[2]), "r"((a)[3]), \
                   "r"(b0), "r"(b1))

// ---------------------------------------------------------------------------
// Stage 0: prep_static — W1 transpose + enc/dec fp16 conversion. 350 CTAs.
// ---------------------------------------------------------------------------
__global__ void __launch_bounds__(256)
prep_static(const float* __restrict__ enc,
            const float* __restrict__ dec,
            const float* __restrict__ W1,
            __half* __restrict__ Ae,
            __half* __restrict__ Ad,
            __half* __restrict__ W1T)
{
    const int tid = threadIdx.x;
    const int bx  = blockIdx.x;

    if (bx < 200) {                       // W1: [1280,640] -> g_W1T[h][d]
        __shared__ float tile[64][65];
        const int h0 = (bx % 10) * 64;
        const int d0 = (bx / 10) * 64;
        const int x  = tid & 63;
        const int yq = tid >> 6;
        #pragma unroll
        for (int j = 0; j < 16; j++) {
            int r = yq + j * 4;
            tile[r][x] = W1[(size_t)(d0 + r) * HH + h0 + x];
        }
        __syncthreads();
        #pragma unroll
        for (int j = 0; j < 16; j++) {
            int ny = yq + j * 4;
            W1T[(size_t)(h0 + ny) * DTOT + d0 + x] =
                __float2half_rn(tile[x][ny]);
        }
        return;
    }

    const int cb = bx - 200;
    const float* __restrict__ src;
    __half* __restrict__ dst;
    size_t off;
    if (cb < 100) { src = enc; dst = Ae; off = (size_t)cb * 4096; }
    else          { src = dec; dst = Ad; off = (size_t)(cb - 100) * 4096; }

    #pragma unroll
    for (int i = 0; i < 4; i++) {
        const size_t idx = off + (size_t)i * 1024 + tid * 4;
        float4 v = *(const float4*)&src[idx];
        __half h[4];
        h[0] = __float2half_rn(v.x);
        h[1] = __float2half_rn(v.y);
        h[2] = __float2half_rn(v.z);
        h[3] = __float2half_rn(v.w);
        *(uint2*)&dst[idx] = *(uint2*)h;
    }
}

// ---------------------------------------------------------------------------
// Stage 1: HMMA projection GEMM + W2 transpose (overlapped in one grid).
// ---------------------------------------------------------------------------
#define PSTG 24576u
#define PROJ_SMEM (3 * 24576)

__device__ __forceinline__ void proj_load(uint32_t sbuf,
                                          const __half* __restrict__ aB,
                                          const __half* __restrict__ bB,
                                          int k0)
{
    const int tid = threadIdx.x;
    #pragma unroll
    for (int i = 0; i < 4; i++) {
        int ci = tid + i * 128;
        int row = ci >> 3;
        int ck = ci & 7;
        uint32_t so = sbuf + row * 128 + ((ck ^ (row & 7)) << 4);
        CP_ASYNC16(so, aB + (size_t)row * DE + k0 + ck * 8);
    }
    #pragma unroll
    for (int i = 0; i < 8; i++) {
        int ci = tid + i * 128;
        int row = ci >> 3;
        int ck = ci & 7;
        uint32_t so = sbuf + 8192u + row * 128 + ((ck ^ (row & 7)) << 4);
        CP_ASYNC16(so, bB + (size_t)row * DTOT + k0 + ck * 8);
    }
}

__global__ void __launch_bounds__(128, 2)
proj_gemm(const __half* __restrict__ Ae,
          const __half* __restrict__ Ad,
          const __half* __restrict__ W1T,
          const float* __restrict__ b1,
          const float* __restrict__ W2,
          float* __restrict__ pe,
          float* __restrict__ pd,
          __half* __restrict__ Bt)
{
    extern __shared__ __align__(1024) char smem[];
    const int tid = threadIdx.x;

    if (blockIdx.y >= 15) {
        // ---- W2 transpose tile: Bt[n][k] = fp16(W2[k][n]), 64x64 ----
        float (*tile)[65] = reinterpret_cast<float(*)[65]>(smem);
        const int tt = (blockIdx.y - 15) * 5 + blockIdx.x;
        const int n0 = (tt & 15) * 64;
        const int k0 = (tt >> 4) * 64;
        const int x  = tid & 63;
        const int yq = tid >> 6;
        #pragma unroll
        for (int j = 0; j < 32; j++) {
            int r = yq + j * 2;
            tile[r][x] = W2[(size_t)(k0 + r) * VV + n0 + x];
        }
        __syncthreads();
        #pragma unroll
        for (int j = 0; j < 32; j++) {
            int ny = yq + j * 2;
            Bt[(size_t)(n0 + ny) * HH + k0 + x] = __float2half_rn(tile[x][ny]);
        }
        return;
    }

    const uint32_t sb = smem_u32(smem);
    const int lane = tid & 31;
    const int wn   = tid >> 5;
    const int n0   = blockIdx.x * 128;
    const bool is_dec = (blockIdx.y >= 10);
    const int m0   = (is_dec ? (blockIdx.y - 10) : blockIdx.y) * 64;
    const int dof  = is_dec ? DE : 0;

    const __half* __restrict__ aB = (is_dec ? Ad : Ae) + (size_t)m0 * DE;
    const __half* __restrict__ bB = W1T + (size_t)n0 * DTOT + dof;
    float* __restrict__ C         = is_dec ? pd : pe;

    const int lml = lane & 15;
    const int lmh = lane >> 4;

    float acc[4][4][4];
    #pragma unroll
    for (int a = 0; a < 4; a++)
        #pragma unroll
        for (int n = 0; n < 4; n++)
            #pragma unroll
            for (int i = 0; i < 4; i++) acc[a][n][i] = 0.0f;

    proj_load(sb,        aB, bB, 0);
    CP_COMMIT();
    proj_load(sb + PSTG, aB, bB, BK);
    CP_COMMIT();
    CP_WAIT1();
    __syncthreads();

    #pragma unroll
    for (int c = 0; c < 10; c++) {
        const uint32_t sbuf = sb + (uint32_t)(c % STAGES) * PSTG;

        if (c + 2 < 10) {
            proj_load(sb + (uint32_t)((c + 2) % STAGES) * PSTG,
                      aB, bB, (c + 2) * BK);
            CP_COMMIT();
        }

        #pragma unroll
        for (int ks = 0; ks < 4; ks++) {
            const int ck = 2 * ks + lmh;

            uint32_t af[4][4];
            #pragma unroll
            for (int a = 0; a < 4; a++) {
                uint32_t row = (uint32_t)(a * 16 + lml);
                LDSM4(af[a][0], af[a][1], af[a][2], af[a][3],
                      sbuf + row * 128 + (uint32_t)((ck ^ (row & 7)) << 4));
            }
            uint32_t bf[2][4];
            #pragma unroll
            for (int p = 0; p < 2; p++) {
                uint32_t row = (uint32_t)(wn * 32 + p * 16 + lml);
                LDSM4(bf[p][0], bf[p][1], bf[p][2], bf[p][3],
                      sbuf + 8192u + row * 128 +
                      (uint32_t)((ck ^ (row & 7)) << 4));
            }
            #pragma unroll
            for (int a = 0; a < 4; a++)
                #pragma unroll
                for (int n = 0; n < 4; n++) {
                    int p = n >> 1, s = n & 1;
                    MMA16816(acc[a][n], af[a], bf[p][s], bf[p][s + 2]);
                }
        }

        if (c + 2 < 10) {
            CP_WAIT1();
            __syncthreads();
        } else if (c + 1 < 10) {
            CP_WAIT0();
            __syncthreads();
        }
    }

    #pragma unroll
    for (int n = 0; n < 4; n++) {
        const int col = n0 + wn * 32 + n * 8 + (lane & 3) * 2;
        float2 bb = make_float2(0.0f, 0.0f);
        if (is_dec) bb = *(const float2*)&b1[col];
        #pragma unroll
        for (int a = 0; a < 4; a++) {
            const int r0 = m0 + a * 16 + (lane >> 2);
            float2 o0 = { acc[a][n][0] + bb.x, acc[a][n][1] + bb.y };
            float2 o1 = { acc[a][n][2] + bb.x, acc[a][n][3] + bb.y };
            *(float2*)&C[(size_t)r0 * HH + col]       = o0;
            *(float2*)&C[(size_t)(r0 + 8) * HH + col] = o1;
        }
    }
}

// ---------------------------------------------------------------------------
// Stage 1.5: tiled A-prep. A = fp16(tanh(pe + pd)). grid (U/16, T/16, B*5).
// ---------------------------------------------------------------------------
__global__ void __launch_bounds__(256)
prep_a(__half* __restrict__ A)
{
    __shared__ float4 pe4[16][33];
    __shared__ float4 pd4[16][33];

    const int u0 = blockIdx.x * 16;
    const int t0 = blockIdx.y * 16;
    const int b  = blockIdx.z / 5;
    const int h0 = (blockIdx.z - b * 5) * 128;

    const int tid = threadIdx.x;

    {
        const int r  = tid >> 4;
        const int c4 = tid & 15;
        const float4* pe_g = (const float4*)&g_pe[(size_t)(b * T_ + t0 + r) * HH + h0];
        const float4* pd_g = (const float4*)&g_pd[(size_t)(b * U_ + u0 + r) * HH + h0];
        pe4[r][c4]      = pe_g[c4];
        pe4[r][c4 + 16] = pe_g[c4 + 16];
        pd4[r][c4]      = pd_g[c4];
        pd4[r][c4 + 16] = pd_g[c4 + 16];
    }
    __syncthreads();

    const int u_l = tid >> 4;
    const int seg = tid & 15;

    const float4 d0 = pd4[u_l][seg * 2];
    const float4 d1 = pd4[u_l][seg * 2 + 1];

    #pragma unroll
    for (int t_l = 0; t_l < 16; t_l++) {
        const float4 e0 = pe4[t_l][seg * 2];
        const float4 e1 = pe4[t_l][seg * 2 + 1];

        __half h[8];
        h[0] = __float2half_rn(fast_tanh(e0.x + d0.x));
        h[1] = __float2half_rn(fast_tanh(e0.y + d0.y));
        h[2] = __float2half_rn(fast_tanh(e0.z + d0.z));
        h[3] = __float2half_rn(fast_tanh(e0.w + d0.w));
        h[4] = __float2half_rn(fast_tanh(e1.x + d1.x));
        h[5] = __float2half_rn(fast_tanh(e1.y + d1.y));
        h[6] = __float2half_rn(fast_tanh(e1.z + d1.z));
        h[7] = __float2half_rn(fast_tanh(e1.w + d1.w));

        const size_t row = (size_t)b * TU + (t0 + t_l) * U_ + u0 + u_l;
        *(uint4*)&A[row * HH + h0 + seg * 8] = *(uint4*)h;
    }
}

// ---------------------------------------------------------------------------
// Stage 2: HMMA joint GEMM (R16 config) with 4-WAY split prefetch:
// one 4-cp.async quarter per ks-slice (A0, A1, B0, B1+commit), so every
// LDGSTS burst hides in the MMA shadow of its slice.
// ---------------------------------------------------------------------------
#define STG_STRIDE 32768u
#define SMEM_TOTAL (STAGES * 32768)

// quarter q of the A tile (q=0,1) or B tile (q=0,1): 4 cp.async per thread
__device__ __forceinline__ void load_A_q(uint32_t sbuf,
                                         const __half* __restrict__ aB,
                                         int k0, int q)
{
    const int tid = threadIdx.x;
    #pragma unroll
    for (int i = 0; i < 4; i++) {
        int ci = tid + (q * 4 + i) * 128;
        int row = ci >> 3;
        int ck = ci & 7;
        uint32_t so = sbuf + row * 128 + ((ck ^ (row & 7)) << 4);
        CP_ASYNC16(so, aB + (size_t)row * HH + k0 + ck * 8);
    }
}

__device__ __forceinline__ void load_B_q(uint32_t sbuf,
                                         const __half* __restrict__ bB,
                                         int k0, int q)
{
    const int tid = threadIdx.x;
    #pragma unroll
    for (int i = 0; i < 4; i++) {
        int ci = tid + (q * 4 + i) * 128;
        int row = ci >> 3;
        int ck = ci & 7;
        uint32_t so = sbuf + 16384u + row * 128 + ((ck ^ (row & 7)) << 4);
        CP_ASYNC16(so, bB + (size_t)row * HH + k0 + ck * 8);
    }
}

__global__ void __launch_bounds__(128, 2)
joint_gemm(const __half* __restrict__ A,
           const __half* __restrict__ B,
           const float* __restrict__ b2,
           float* __restrict__ out)
{
    extern __shared__ __align__(1024) char smem[];
    const uint32_t sb = smem_u32(smem);

    const int tid  = threadIdx.x;
    const int lane = tid & 31;
    const int wid  = tid >> 5;
    const int wm   = wid & 1;
    const int wn   = wid >> 1;
    const int n0   = blockIdx.x * BN;
    const int m0   = blockIdx.y * BM;

    const __half* __restrict__ aB = A + (size_t)m0 * HH;
    const __half* __restrict__ bB = B + (size_t)n0 * HH;

    const int lml = lane & 15;
    const int lmh = lane >> 4;

    // prefetch epilogue bias (latency hidden under mainloop)
    float2 bb[8];
    #pragma unroll
    for (int n = 0; n < 8; n++)
        bb[n] = *(const float2*)&b2[n0 + wn * 64 + n * 8 + (lane & 3) * 2];

    float acc[4][8][4];
    #pragma unroll
    for (int a = 0; a < 4; a++)
        #pragma unroll
        for (int n = 0; n < 8; n++)
            #pragma unroll
            for (int i = 0; i < 4; i++) acc[a][n][i] = 0.0f;

    load_A_q(sb, aB, 0, 0); load_A_q(sb, aB, 0, 1);
    load_B_q(sb, bB, 0, 0); load_B_q(sb, bB, 0, 1);
    CP_COMMIT();
    load_A_q(sb + STG_STRIDE, aB, BK, 0); load_A_q(sb + STG_STRIDE, aB, BK, 1);
    load_B_q(sb + STG_STRIDE, bB, BK, 0); load_B_q(sb + STG_STRIDE, bB, BK, 1);
    CP_COMMIT();
    CP_WAIT1();
    __syncthreads();

    #pragma unroll
    for (int c = 0; c < KITERS; c++) {
        const uint32_t sbuf = sb + (uint32_t)(c % STAGES) * STG_STRIDE;
        const uint32_t pbuf = sb + (uint32_t)((c + 2) % STAGES) * STG_STRIDE;
        const bool do_pf = (c + 2 < KITERS);
        const int kpf = (c + 2) * BK;

        #pragma unroll
        for (int ks = 0; ks < 4; ks++) {
            const int ck = 2 * ks + lmh;

            uint32_t af[4][4];
            #pragma unroll
            for (int a = 0; a < 4; a++) {
                uint32_t row = (uint32_t)(wm * 64 + a * 16 + lml);
                LDSM4(af[a][0], af[a][1], af[a][2], af[a][3],
                      sbuf + row * 128 + (uint32_t)((ck ^ (row & 7)) << 4));
            }
            uint32_t bf[4][4];
            #pragma unroll
            for (int p = 0; p < 4; p++) {
                uint32_t row = (uint32_t)(wn * 64 + p * 16 + lml);
                LDSM4(bf[p][0], bf[p][1], bf[p][2], bf[p][3],
                      sbuf + 16384u + row * 128 +
                      (uint32_t)((ck ^ (row & 7)) << 4));
            }
            #pragma unroll
            for (int a = 0; a < 4; a++)
                #pragma unroll
                for (int n = 0; n < 8; n++) {
                    int p = n >> 1, s = n & 1;
                    MMA16816(acc[a][n], af[a], bf[p][s], bf[p][s + 2]);
                }

            // one prefetch quarter per ks-slice, commit on the last
            if (do_pf) {
                if (ks == 0) load_A_q(pbuf, aB, kpf, 0);
                if (ks == 1) load_A_q(pbuf, aB, kpf, 1);
                if (ks == 2) load_B_q(pbuf, bB, kpf, 0);
                if (ks == 3) {
                    load_B_q(pbuf, bB, kpf, 1);
                    CP_COMMIT();
                }
            }
        }

        if (c + 2 < KITERS) {
            CP_WAIT1();
            __syncthreads();
        } else if (c + 1 < KITERS) {
            CP_WAIT0();
            __syncthreads();
        }
        // last iter: no barrier — epilogue reads only registers
    }

    #pragma unroll
    for (int n = 0; n < 8; n++) {
        const int col = n0 + wn * 64 + n * 8 + (lane & 3) * 2;
        #pragma unroll
        for (int a = 0; a < 4; a++) {
            const size_t r0 = (size_t)m0 + wm * 64 + a * 16 + (lane >> 2);
            float2 o0 = { acc[a][n][0] + bb[n].x, acc[a][n][1] + bb[n].y };
            float2 o1 = { acc[a][n][2] + bb[n].x, acc[a][n][3] + bb[n].y };
            *(float2*)&out[r0 * VV + col]       = o0;
            *(float2*)&out[(r0 + 8) * VV + col] = o1;
        }
    }
}

// ---------------------------------------------------------------------------
// Launch: 4 kernels
// ---------------------------------------------------------------------------
extern "C" void kernel_launch(void* const* d_in, const int* in_sizes, int n_in,
                              void* d_out, int out_size)
{
    const float* enc = (const float*)d_in[0];
    const float* dec = (const float*)d_in[1];
    const float* W1  = (const float*)d_in[2];
    const float* b1  = (const float*)d_in[3];
    const float* W2  = (const float*)d_in[4];
    const float* b2  = (const float*)d_in[5];
    float* out = (float*)d_out;

    float *pe = nullptr, *pd = nullptr;
    __half *ga = nullptr, *gb = nullptr, *gae = nullptr, *gad = nullptr,
           *gw1t = nullptr;
    cudaGetSymbolAddress((void**)&pe,   g_pe);
    cudaGetSymbolAddress((void**)&pd,   g_pd);
    cudaGetSymbolAddress((void**)&ga,   g_A);
    cudaGetSymbolAddress((void**)&gb,   g_B);
    cudaGetSymbolAddress((void**)&gae,  g_Ae);
    cudaGetSymbolAddress((void**)&gad,  g_Ad);
    cudaGetSymbolAddress((void**)&gw1t, g_W1T);

    cudaFuncSetAttribute(joint_gemm,
                         cudaFuncAttributeMaxDynamicSharedMemorySize, SMEM_TOTAL);
    cudaFuncSetAttribute(proj_gemm,
                         cudaFuncAttributeMaxDynamicSharedMemorySize, PROJ_SMEM);

    prep_static<<<350, 256>>>(enc, dec, W1, gae, gad, gw1t);
    proj_gemm<<<dim3(HH / 128, 47), 128, PROJ_SMEM>>>(gae, gad, gw1t, b1, W2,
                                                      pe, pd, gb);
    prep_a<<<dim3(U_ / 16, T_ / 16, B_ * 5), 256>>>(ga);
    joint_gemm<<<dim3(VV / BN, MTOT / BM), 128, SMEM_TOTAL>>>(ga, gb, b2, out);
}